// round 12
// baseline (speedup 1.0000x reference)
#include <cuda_runtime.h>
#include <cstdint>

#define BB      16
#define HH      32
#define DD      128
#define HIDDEN  4096      // HH*DD
#define MB      128
#define BSZ     16
#define SMAX    2048      // MB*BSZ
#define SPLITS  16
#define SPLIT_S (SMAX / SPLITS)   // 128
#define NW      4                 // warps per CTA
#define NT      (NW * 32)         // 128 threads
#define EPS     1e-6f
#define SCALE   0.08838834764831845f   // 1/sqrt(128)

#define P       16                // positions per pipeline stage
#define NSTAGE  3                 // smem ring depth
#define ROWF    132               // padded row stride in floats (528 B)
#define STAGE_F (P * ROWF)        // floats per stage per tensor
#define SMEM_DYN_BYTES (NSTAGE * STAGE_F * 2 * 4)   // K + V rings = 50688 B

// Persistent device scratch (counters reset by combining CTA -> replay safe)
__device__ float g_q [BB * HIDDEN];
__device__ float g_pm[BB * HH * SPLITS];
__device__ float g_pl[BB * HH * SPLITS];
__device__ float g_po[BB * HH * SPLITS * DD];
__device__ int   g_cnt[BB * HH];

__device__ __forceinline__ void cp16(unsigned int dst, const void* src) {
    asm volatile("cp.async.cg.shared.global [%0], [%1], 16;"
                 :: "r"(dst), "l"(src) : "memory");
}

// ---------------------------------------------------------------------------
// Kernel 1: RMSNorm -> q.   grid = B*H = 512, block = 256.
// ---------------------------------------------------------------------------
__global__ void __launch_bounds__(256) rms_kernel(const float* __restrict__ x,
                                                  const float* __restrict__ w) {
    int bh  = blockIdx.x;
    int h   = bh & (HH - 1);
    int b   = bh >> 5;
    int tid = threadIdx.x;
    int warp = tid >> 5, lane = tid & 31;

    const float4* xp = (const float4*)(x + (size_t)b * HIDDEN);

    float s = 0.f;
#pragma unroll
    for (int i = 0; i < 4; i++) {
        float4 v = xp[tid + i * 256];
        s += v.x * v.x + v.y * v.y + v.z * v.z + v.w * v.w;
    }
    __shared__ float red[8];
#pragma unroll
    for (int o = 16; o; o >>= 1) s += __shfl_xor_sync(0xffffffffu, s, o);
    if (lane == 0) red[warp] = s;
    __syncthreads();
    float t = red[0];
#pragma unroll
    for (int i = 1; i < 8; i++) t += red[i];
    float inv = rsqrtf(t * (1.0f / HIDDEN) + EPS);

    if (tid < 32) {
        float4 hv = xp[h * 32 + tid];
        float4 wv = ((const float4*)w)[h * 32 + tid];
        float4 q;
        q.x = hv.x * inv * wv.x;
        q.y = hv.y * inv * wv.y;
        q.z = hv.z * inv * wv.z;
        q.w = hv.w * inv * wv.w;
        ((float4*)(g_q + (size_t)b * HIDDEN + h * DD))[tid] = q;
    }
}

// ---------------------------------------------------------------------------
// Kernel 2: cp.async-pipelined single-pass flash-decoding partial + combine.
// grid = B*H*SPLITS = 8192, block = 128 (4 warps).
// 3-stage smem ring of 16-position K+V tiles; compute overlaps deep copies.
// ---------------------------------------------------------------------------
__global__ void __launch_bounds__(NT) attn_partial(
        const float* __restrict__ hidden,
        const float* __restrict__ kc,
        const float* __restrict__ vc,
        const int*   __restrict__ bt,
        const int*   __restrict__ ctx,
        float*       __restrict__ out) {

    extern __shared__ float smdyn[];
    float* kbuf = smdyn;                       // [NSTAGE][P][ROWF]
    float* vbuf = smdyn + NSTAGE * STAGE_F;    // [NSTAGE][P][ROWF]

    __shared__ int   sbase[SPLIT_S];
    __shared__ float red_m[NW], red_l[NW];
    __shared__ float accs[NW * DD];
    __shared__ bool  isLast;

    int idx   = blockIdx.x;
    int split = idx & (SPLITS - 1);
    int bh    = idx >> 4;
    int h     = bh & (HH - 1);
    int b     = bh >> 5;
    int tid   = threadIdx.x;
    int warp  = tid >> 5;
    int lane  = tid & 31;

    int n_ctx = ctx[b];
    int start = split * SPLIT_S;
    int end   = min(n_ctx, start + SPLIT_S);
    int n     = end - start;             // may be <= 0

    if (n > 0) {
        // ---- prologue: per-position row offsets (1 elem / thread) ----
        if (tid < n) {
            int s   = start + tid;
            int blk = __ldg(&bt[b * MB + (s >> 4)]);
            sbase[tid] = ((blk * BSZ + (s & 15)) * HH + h) * DD;
        }
        float4 qv = ((const float4*)(g_q + (size_t)b * HIDDEN + h * DD))[lane];
        __syncthreads();   // sbase visible before any copies use it

        unsigned int kaddr = (unsigned int)__cvta_generic_to_shared(kbuf);
        unsigned int vaddr = (unsigned int)__cvta_generic_to_shared(vbuf);

        int nst = (n + P - 1) / P;

        // per-thread copy role: position tid>>3 of the stage, chunks (tid&7)+8j
        int cpos = tid >> 3;
        int cch  = tid & 7;

        auto copy_stage = [&](int s) {
            if (s < nst) {
                int pg = s * P + cpos;
                if (pg < n) {
                    const char* ks = (const char*)(kc + sbase[pg]);
                    const char* vs = (const char*)(vc + sbase[pg]);
                    int row = (s % NSTAGE) * P + cpos;
                    unsigned int kd = kaddr + (unsigned int)(row * ROWF * 4);
                    unsigned int vd = vaddr + (unsigned int)(row * ROWF * 4);
#pragma unroll
                    for (int j = 0; j < 4; j++) {
                        int off = (cch + 8 * j) << 4;
                        cp16(kd + off, ks + off);
                        cp16(vd + off, vs + off);
                    }
                }
            }
            asm volatile("cp.async.commit_group;" ::: "memory");
        };

        copy_stage(0);
        copy_stage(1);

        float4 acc = make_float4(0.f, 0.f, 0.f, 0.f);
        float  mw  = -1e30f;
        float  lw  = 0.f;
        int    pw  = warp * 4;   // this warp's position offset within a stage

        for (int s = 0; s < nst; s++) {
            asm volatile("cp.async.wait_group 1;" ::: "memory");
            __syncthreads();            // stage s ready; compute(s-1) done by all
            copy_stage(s + 2);          // overwrites buffer (s-1)%NSTAGE

            int buf  = s % NSTAGE;
            int cnt  = min(P, n - s * P);   // 1..16 valid positions this stage

            float p[4];
#pragma unroll
            for (int j = 0; j < 4; j++) {
                p[j] = 0.f;
                if (pw + j < cnt) {
                    const float4* kr =
                        (const float4*)(kbuf + (buf * P + pw + j) * ROWF);
                    float4 kv = kr[lane];
                    p[j] = qv.x * kv.x + qv.y * kv.y + qv.z * kv.z + qv.w * kv.w;
                }
            }
#pragma unroll
            for (int j = 0; j < 4; j++) {
#pragma unroll
                for (int o = 16; o; o >>= 1)
                    p[j] += __shfl_xor_sync(0xffffffffu, p[j], o);
            }
#pragma unroll
            for (int j = 0; j < 4; j++)
                p[j] = (pw + j < cnt) ? p[j] * SCALE : -1e30f;

            float pm = fmaxf(fmaxf(p[0], p[1]), fmaxf(p[2], p[3]));
            float newm = fmaxf(mw, pm);
            float r    = __expf(mw - newm);

            float e[4];
            float esum = 0.f;
#pragma unroll
            for (int j = 0; j < 4; j++) {
                e[j] = (pw + j < cnt) ? __expf(p[j] - newm) : 0.f;
                esum += e[j];
            }
            lw = lw * r + esum;

            acc.x *= r; acc.y *= r; acc.z *= r; acc.w *= r;
#pragma unroll
            for (int j = 0; j < 4; j++) {
                if (pw + j < cnt) {
                    const float4* vr =
                        (const float4*)(vbuf + (buf * P + pw + j) * ROWF);
                    float4 vv = vr[lane];
                    acc.x += e[j] * vv.x;
                    acc.y += e[j] * vv.y;
                    acc.z += e[j] * vv.z;
                    acc.w += e[j] * vv.w;
                }
            }
            mw = newm;
        }

        // ---- merge NW warp states ----
        if (lane == 0) { red_m[warp] = mw; red_l[warp] = lw; }
        __syncthreads();

        float M = red_m[0];
#pragma unroll
        for (int i = 1; i < NW; i++) M = fmaxf(M, red_m[i]);
        float L = 0.f;
#pragma unroll
        for (int i = 0; i < NW; i++) L += red_l[i] * __expf(red_m[i] - M);

        float sw = __expf(mw - M);   // 0 for warps that saw no positions
        acc.x *= sw; acc.y *= sw; acc.z *= sw; acc.w *= sw;
        ((float4*)accs)[warp * 32 + lane] = acc;
        __syncthreads();

        {
            float a = 0.f;
#pragma unroll
            for (int g = 0; g < NW; g++) a += accs[g * DD + tid];
            g_po[(size_t)idx * DD + tid] = a;
        }
        if (tid == 0) {
            g_pm[idx] = M;
            g_pl[idx] = L;
        }
    } else {
        if (tid == 0) { g_pm[idx] = -1e30f; g_pl[idx] = 0.f; }
    }

    // ---- publish + last-CTA combine ----
    __threadfence();
    if (tid == 0)
        isLast = (atomicAdd(&g_cnt[bh], 1) == SPLITS - 1);
    __syncthreads();

    if (isLast) {
        __threadfence();   // acquire: make peers' partials visible
        {
            int d = tid;
            float M = -1e30f;
#pragma unroll
            for (int i = 0; i < SPLITS; i++)
                M = fmaxf(M, g_pm[bh * SPLITS + i]);
            float L = 0.f, A = 0.f;
#pragma unroll
            for (int i = 0; i < SPLITS; i++) {
                float li = g_pl[bh * SPLITS + i];
                if (li > 0.f) {
                    float wgt = __expf(g_pm[bh * SPLITS + i] - M);
                    L += li * wgt;
                    A += wgt * g_po[(size_t)(bh * SPLITS + i) * DD + d];
                }
            }
            int o = bh * DD + d;   // == b*HIDDEN + h*DD + d
            out[o] = hidden[o] + A / L;
        }
        if (tid == 0) g_cnt[bh] = 0;   // reset for next graph replay
    }
}

// ---------------------------------------------------------------------------
extern "C" void kernel_launch(void* const* d_in, const int* in_sizes, int n_in,
                              void* d_out, int out_size) {
    const float* hidden = (const float*)d_in[0];
    const float* kc     = (const float*)d_in[1];
    const float* vc     = (const float*)d_in[2];
    const int*   bt     = (const int*)  d_in[3];
    const int*   ctx    = (const int*)  d_in[4];
    const float* w      = (const float*)d_in[5];
    float*       out    = (float*)d_out;

    cudaFuncSetAttribute(attn_partial,
                         cudaFuncAttributeMaxDynamicSharedMemorySize,
                         SMEM_DYN_BYTES);

    rms_kernel  <<<BB * HH,          256>>>(hidden, w);
    attn_partial<<<BB * HH * SPLITS, NT, SMEM_DYN_BYTES>>>(hidden, kc, vc, bt, ctx, out);
}